// round 1
// baseline (speedup 1.0000x reference)
#include <cuda_runtime.h>
#include <math.h>

#define NA 10000
#define NE 500000
#define NSPEC 119
#define NPAIR (NSPEC*NSPEC)      // 14161
#define EMBSTRIDE 40             // padded from 35, 160B = 16B aligned
#define NEMB (NPAIR*EMBSTRIDE)   // 566440
#define NFEAT 360

// Scratch (no allocations allowed -> device globals)
__device__ int   g_count[NA];
__device__ int   g_off[NA + 1];
__device__ int   g_cursor[NA];
__device__ int   g_sorted[NE];
__device__ float g_emb[NEMB];

// ---------------------------------------------------------------------------
// Prep: zero histogram + build padded/prescaled embedding table.
// Folds rad_norm * EMB_NORM into the coefficients.
// ---------------------------------------------------------------------------
__global__ void k_prep(const float* __restrict__ emb) {
    int i = blockIdx.x * blockDim.x + threadIdx.x;
    if (i < NA) g_count[i] = 0;
    if (i < NEMB) {
        int pair = i / EMBSTRIDE;
        int slot = i - pair * EMBSTRIDE;
        // scale = (2*betta/pi)^0.75 / sqrt(7), betta = 49/36
        float scale = powf(2.0f * (49.0f / 36.0f) / 3.14159265358979f, 0.75f) * rsqrtf(7.0f);
        g_emb[i] = (slot < 35) ? emb[pair * 35 + slot] * scale : 0.0f;
    }
}

// ---------------------------------------------------------------------------
// Histogram of edges per destination atom j = neighbor_idxs[1][e]
// ---------------------------------------------------------------------------
__global__ void k_hist(const int* __restrict__ nbr) {
    int e = blockIdx.x * blockDim.x + threadIdx.x;
    if (e < NE) atomicAdd(&g_count[nbr[NE + e]], 1);
}

// ---------------------------------------------------------------------------
// Single-block exclusive scan over 10000 counts -> offsets, cursor
// ---------------------------------------------------------------------------
__global__ void k_scan() {
    __shared__ int sh[1024];
    int t = threadIdx.x;
    const int CH = 10;   // 1024*10 >= 10000
    int loc[CH];
    int sum = 0;
#pragma unroll
    for (int c = 0; c < CH; c++) {
        int idx = t * CH + c;
        loc[c] = sum;
        sum += (idx < NA) ? g_count[idx] : 0;
    }
    sh[t] = sum;
    __syncthreads();
    for (int off = 1; off < 1024; off <<= 1) {
        int v = (t >= off) ? sh[t - off] : 0;
        __syncthreads();
        sh[t] += v;
        __syncthreads();
    }
    int exc = (t > 0) ? sh[t - 1] : 0;
#pragma unroll
    for (int c = 0; c < CH; c++) {
        int idx = t * CH + c;
        if (idx < NA) {
            int o = exc + loc[c];
            g_off[idx] = o;
            g_cursor[idx] = o;
        }
    }
    if (t == 1023) g_off[NA] = sh[1023];
}

// ---------------------------------------------------------------------------
// Scatter edge ids into per-atom contiguous runs
// ---------------------------------------------------------------------------
__global__ void k_scatter(const int* __restrict__ nbr) {
    int e = blockIdx.x * blockDim.x + threadIdx.x;
    if (e < NE) {
        int j = nbr[NE + e];
        int pos = atomicAdd(&g_cursor[j], 1);
        g_sorted[pos] = e;
    }
}

// Symmetric index helpers (fold to constants after unroll)
__device__ __forceinline__ int s2i(int i, int j) {
    return (i >= j) ? (i * (i + 1) / 2 + j) : (j * (j + 1) / 2 + i);
}
__device__ __forceinline__ int s3i(int i, int j, int k) {
    int a = i > j ? i : j;
    int b = i > j ? j : i;
    int c;
    if (k >= a)      { c = b; b = a; a = k; }
    else if (k >= b) { c = b; b = k; }
    else             { c = k; }
    return a * (a + 1) * (a + 2) / 6 + b * (b + 1) / 2 + c;
}

// ---------------------------------------------------------------------------
// Main: one thread per atom. Register-resident symmetric moment accumulators
// (5 x 20 = 100 floats), then fully unrolled contractions -> 360 features.
// ---------------------------------------------------------------------------
__global__ void __launch_bounds__(32) k_main(const float* __restrict__ drv,
                                             const int* __restrict__ Z,
                                             const int* __restrict__ nbr,
                                             float* __restrict__ outbuf) {
    int a = blockIdx.x * blockDim.x + threadIdx.x;
    if (a >= NA) return;

    float A0[5] = {0.f, 0.f, 0.f, 0.f, 0.f};
    float A1[5][3];
    float A2[5][6];
    float A3[5][10];
#pragma unroll
    for (int r = 0; r < 5; r++) {
#pragma unroll
        for (int u = 0; u < 3; u++) A1[r][u] = 0.f;
#pragma unroll
        for (int u = 0; u < 6; u++) A2[r][u] = 0.f;
#pragma unroll
        for (int u = 0; u < 10; u++) A3[r][u] = 0.f;
    }

    const int Zj = Z[a];
    const int beg = g_off[a];
    const int end = g_off[a + 1];

    const float BETTA = 49.0f / 36.0f;
    const float PIR = 3.14159265358979f / 6.0f;  // pi / R_MAX
    const float SH0 = 0.5f;
    const float DSH = 5.5f / 7.0f;

    for (int p = beg; p < end; ++p) {
        int e = g_sorted[p];
        int ii = nbr[e];
        int Zi = Z[ii];
        float x = drv[3 * e + 0];
        float y = drv[3 * e + 1];
        float z = drv[3 * e + 2];
        const float4* q4 = (const float4*)(g_emb + (Zi * NSPEC + Zj) * EMBSTRIDE);
        float4 qa = q4[0], qb = q4[1], qc = q4[2], qd = q4[3], qe = q4[4];
        float4 qf = q4[5], qg = q4[6], qh = q4[7], qi = q4[8];
        float q[36] = {qa.x, qa.y, qa.z, qa.w, qb.x, qb.y, qb.z, qb.w,
                       qc.x, qc.y, qc.z, qc.w, qd.x, qd.y, qd.z, qd.w,
                       qe.x, qe.y, qe.z, qe.w, qf.x, qf.y, qf.z, qf.w,
                       qg.x, qg.y, qg.z, qg.w, qh.x, qh.y, qh.z, qh.w,
                       qi.x, qi.y, qi.z, qi.w};

        float dr = sqrtf(x * x + y * y + z * z);
        float inv = 1.0f / (dr + 1e-5f);
        float dnx = x * inv, dny = y * inv, dnz = z * inv;
        float cut = 0.5f * (__cosf(fminf(dr, 6.0f) * PIR) + 1.0f);

        float basis[7];
#pragma unroll
        for (int b = 0; b < 7; b++) {
            float d = dr - (SH0 + DSH * (float)b);
            basis[b] = __expf(-BETTA * d * d);
        }

        float radial[5];
#pragma unroll
        for (int r = 0; r < 5; r++) {
            float s = 0.f;
#pragma unroll
            for (int b = 0; b < 7; b++) s += q[r * 7 + b] * basis[b];
            radial[r] = s * cut;
        }

        float g2[6] = {dnx * dnx, dny * dnx, dny * dny, dnz * dnx, dnz * dny, dnz * dnz};
        float g3[10] = {g2[0] * dnx, g2[1] * dnx, g2[2] * dnx, g2[2] * dny,
                        g2[3] * dnx, g2[4] * dnx, g2[4] * dny, g2[5] * dnx,
                        g2[5] * dny, g2[5] * dnz};
#pragma unroll
        for (int r = 0; r < 5; r++) {
            float s = radial[r];
            A0[r] += s;
            A1[r][0] += s * dnx;
            A1[r][1] += s * dny;
            A1[r][2] += s * dnz;
#pragma unroll
            for (int u = 0; u < 6; u++) A2[r][u] += s * g2[u];
#pragma unroll
            for (int u = 0; u < 10; u++) A3[r][u] += s * g3[u];
        }
    }

    // ----- contractions -----
    float* out = outbuf + (size_t)a * NFEAT;
    int o = 0;

    // c0 (5)
#pragma unroll
    for (int r = 0; r < 5; r++) out[o++] = A0[r];

    // c1 (15): sum_i M1[r,i] M1[s,i]
#pragma unroll
    for (int r = 0; r < 5; r++)
#pragma unroll
        for (int s = 0; s <= r; s++) {
            float v = 0.f;
#pragma unroll
            for (int i = 0; i < 3; i++) v += A1[r][i] * A1[s][i];
            out[o++] = v;
        }

    // c2 (15): weighted symmetric dot of M2
    {
        const float W2[6] = {1.f, 2.f, 1.f, 2.f, 2.f, 1.f};
#pragma unroll
        for (int r = 0; r < 5; r++)
#pragma unroll
            for (int s = 0; s <= r; s++) {
                float v = 0.f;
#pragma unroll
                for (int u = 0; u < 6; u++) v += W2[u] * A2[r][u] * A2[s][u];
                out[o++] = v;
            }
    }

    // c3 (15): weighted symmetric dot of M3
    {
        const float W3[10] = {1.f, 3.f, 3.f, 1.f, 3.f, 6.f, 3.f, 3.f, 3.f, 1.f};
#pragma unroll
        for (int r = 0; r < 5; r++)
#pragma unroll
            for (int s = 0; s <= r; s++) {
                float v = 0.f;
#pragma unroll
                for (int u = 0; u < 10; u++) v += W3[u] * A3[r][u] * A3[s][u];
                out[o++] = v;
            }
    }

    // c4 (35): sum_{ijk} M2[r,ij] M2[s,ik] M2[t,jk], (r,s,t) lower-triangular
#pragma unroll
    for (int r = 0; r < 5; r++)
#pragma unroll
        for (int s = 0; s <= r; s++)
#pragma unroll
            for (int t = 0; t <= s; t++) {
                float v = 0.f;
#pragma unroll
                for (int i = 0; i < 3; i++)
#pragma unroll
                    for (int j = 0; j < 3; j++)
#pragma unroll
                        for (int k = 0; k < 3; k++)
                            v += A2[r][s2i(i, j)] * A2[s][s2i(i, k)] * A2[t][s2i(j, k)];
                out[o++] = v;
            }

    // c5 (75): sum_ij M1[r,i] M1[s,j] M2[t,ij], pairs (r,s) outer, t inner
#pragma unroll
    for (int r = 0; r < 5; r++)
#pragma unroll
        for (int s = 0; s <= r; s++)
#pragma unroll
            for (int t = 0; t < 5; t++) {
                float v = 0.f;
#pragma unroll
                for (int i = 0; i < 3; i++)
#pragma unroll
                    for (int j = 0; j < 3; j++)
                        v += A1[r][i] * A1[s][j] * A2[t][s2i(i, j)];
                out[o++] = v;
            }

    // c6 (75): sum_{ijkl} M3[r,ijk] M3[s,ijl] M2[t,kl]
#pragma unroll
    for (int r = 0; r < 5; r++)
#pragma unroll
        for (int s = 0; s <= r; s++) {
            float B[9];
#pragma unroll
            for (int k = 0; k < 3; k++)
#pragma unroll
                for (int l = 0; l < 3; l++) {
                    float u = 0.f;
#pragma unroll
                    for (int i = 0; i < 3; i++)
#pragma unroll
                        for (int j = 0; j < 3; j++)
                            u += A3[r][s3i(i, j, k)] * A3[s][s3i(i, j, l)];
                    B[k * 3 + l] = u;
                }
#pragma unroll
            for (int t = 0; t < 5; t++) {
                float v = 0.f;
#pragma unroll
                for (int k = 0; k < 3; k++)
#pragma unroll
                    for (int l = 0; l < 3; l++)
                        v += B[k * 3 + l] * A2[t][s2i(k, l)];
                out[o++] = v;
            }
        }

    // c7 (125): sum_{ijk} M3[r,ijk] M2[s,ij] M1[t,k], full (r,s,t)
#pragma unroll
    for (int r = 0; r < 5; r++)
#pragma unroll
        for (int s = 0; s < 5; s++) {
            float C[3];
#pragma unroll
            for (int k = 0; k < 3; k++) {
                float u = 0.f;
#pragma unroll
                for (int i = 0; i < 3; i++)
#pragma unroll
                    for (int j = 0; j < 3; j++)
                        u += A3[r][s3i(i, j, k)] * A2[s][s2i(i, j)];
                C[k] = u;
            }
#pragma unroll
            for (int t = 0; t < 5; t++) {
                float v = 0.f;
#pragma unroll
                for (int k = 0; k < 3; k++) v += C[k] * A1[t][k];
                out[o++] = v;
            }
        }
}

extern "C" void kernel_launch(void* const* d_in, const int* in_sizes, int n_in,
                              void* d_out, int out_size) {
    const float* dr_vec = (const float*)d_in[0];
    const int*   Z      = (const int*)d_in[1];
    const int*   nbr    = (const int*)d_in[2];
    const float* emb    = (const float*)d_in[3];
    float*       out    = (float*)d_out;

    k_prep<<<(NEMB + 255) / 256, 256>>>(emb);
    k_hist<<<(NE + 255) / 256, 256>>>(nbr);
    k_scan<<<1, 1024>>>();
    k_scatter<<<(NE + 255) / 256, 256>>>(nbr);
    k_main<<<(NA + 31) / 32, 32>>>(dr_vec, Z, nbr, out);
}

// round 3
// speedup vs baseline: 1.5097x; 1.5097x over previous
#include <cuda_runtime.h>
#include <math.h>

#define NA 10000
#define NE 500000
#define NSPEC 119
#define NPAIR (NSPEC*NSPEC)      // 14161
#define EMBSTRIDE 40             // padded from 35, 160B = 16B aligned
#define NEMB (NPAIR*EMBSTRIDE)   // 566440
#define NFEAT 360

// Scratch (no allocations allowed -> device globals)
__device__ int    g_count[NA];
__device__ int    g_off[NA + 1];
__device__ int    g_cursor[NA];
__device__ float  g_emb[NEMB];
__device__ float4 g_edata[NE * 2];   // per sorted position: {r0..r3},{r4,dnx,dny,dnz}

// ---------------------------------------------------------------------------
// Prep: zero histogram + build padded/prescaled embedding table.
// ---------------------------------------------------------------------------
__global__ void k_prep(const float* __restrict__ emb) {
    int i = blockIdx.x * blockDim.x + threadIdx.x;
    if (i < NA) g_count[i] = 0;
    if (i < NEMB) {
        int pair = i / EMBSTRIDE;
        int slot = i - pair * EMBSTRIDE;
        float scale = powf(2.0f * (49.0f / 36.0f) / 3.14159265358979f, 0.75f) * rsqrtf(7.0f);
        g_emb[i] = (slot < 35) ? emb[pair * 35 + slot] * scale : 0.0f;
    }
}

// ---------------------------------------------------------------------------
// Histogram of edges per destination atom, 4 edges/thread for MLP
// ---------------------------------------------------------------------------
__global__ void k_hist(const int* __restrict__ nbr) {
    int base = (blockIdx.x * blockDim.x + threadIdx.x) * 4;
#pragma unroll
    for (int k = 0; k < 4; k++) {
        int e = base + k;
        if (e < NE) atomicAdd(&g_count[nbr[NE + e]], 1);
    }
}

// ---------------------------------------------------------------------------
// Single-block exclusive scan over 10000 counts -> offsets, cursor
// ---------------------------------------------------------------------------
__global__ void k_scan() {
    __shared__ int sh[1024];
    int t = threadIdx.x;
    const int CH = 10;
    int loc[CH];
    int sum = 0;
#pragma unroll
    for (int c = 0; c < CH; c++) {
        int idx = t * CH + c;
        loc[c] = sum;
        sum += (idx < NA) ? g_count[idx] : 0;
    }
    sh[t] = sum;
    __syncthreads();
    for (int off = 1; off < 1024; off <<= 1) {
        int v = (t >= off) ? sh[t - off] : 0;
        __syncthreads();
        sh[t] += v;
        __syncthreads();
    }
    int exc = (t > 0) ? sh[t - 1] : 0;
#pragma unroll
    for (int c = 0; c < CH; c++) {
        int idx = t * CH + c;
        if (idx < NA) {
            int o = exc + loc[c];
            g_off[idx] = o;
            g_cursor[idx] = o;
        }
    }
    if (t == 1023) g_off[NA] = sh[1023];
}

// ---------------------------------------------------------------------------
// Edge phase: fused scatter + per-edge radial/direction compute.
// Fully edge-parallel -> gather-chain latency hidden by occupancy.
// Writes 32B per edge at its sorted position.
// ---------------------------------------------------------------------------
__global__ void __launch_bounds__(256) k_edge(const float* __restrict__ drv,
                                              const int* __restrict__ Z,
                                              const int* __restrict__ nbr) {
    const float BETTA = 49.0f / 36.0f;
    const float PIR = 3.14159265358979f / 6.0f;
    const float SH0 = 0.5f;
    const float DSH = 5.5f / 7.0f;

    int base = (blockIdx.x * blockDim.x + threadIdx.x) * 2;
#pragma unroll
    for (int k = 0; k < 2; k++) {
        int e = base + k;
        if (e >= NE) continue;
        int ii = nbr[e];
        int jj = nbr[NE + e];
        int Zi = Z[ii];
        int Zj = Z[jj];
        int pos = atomicAdd(&g_cursor[jj], 1);

        float x = drv[3 * e + 0];
        float y = drv[3 * e + 1];
        float z = drv[3 * e + 2];

        const float4* q4 = (const float4*)(g_emb + (Zi * NSPEC + Zj) * EMBSTRIDE);
        float4 qa = q4[0], qb = q4[1], qc = q4[2], qd = q4[3], qe = q4[4];
        float4 qf = q4[5], qg = q4[6], qh = q4[7], qi = q4[8];
        float q[36] = {qa.x, qa.y, qa.z, qa.w, qb.x, qb.y, qb.z, qb.w,
                       qc.x, qc.y, qc.z, qc.w, qd.x, qd.y, qd.z, qd.w,
                       qe.x, qe.y, qe.z, qe.w, qf.x, qf.y, qf.z, qf.w,
                       qg.x, qg.y, qg.z, qg.w, qh.x, qh.y, qh.z, qh.w,
                       qi.x, qi.y, qi.z, qi.w};

        float dr = sqrtf(x * x + y * y + z * z);
        float inv = 1.0f / (dr + 1e-5f);
        float dnx = x * inv, dny = y * inv, dnz = z * inv;
        float cut = 0.5f * (__cosf(fminf(dr, 6.0f) * PIR) + 1.0f);

        float basis[7];
#pragma unroll
        for (int b = 0; b < 7; b++) {
            float d = dr - (SH0 + DSH * (float)b);
            basis[b] = __expf(-BETTA * d * d);
        }

        float radial[5];
#pragma unroll
        for (int r = 0; r < 5; r++) {
            float s = 0.f;
#pragma unroll
            for (int b = 0; b < 7; b++) s += q[r * 7 + b] * basis[b];
            radial[r] = s * cut;
        }

        g_edata[2 * pos]     = make_float4(radial[0], radial[1], radial[2], radial[3]);
        g_edata[2 * pos + 1] = make_float4(radial[4], dnx, dny, dnz);
    }
}

// Symmetric index helpers (fold to constants after unroll)
__device__ __forceinline__ int s2i(int i, int j) {
    return (i >= j) ? (i * (i + 1) / 2 + j) : (j * (j + 1) / 2 + i);
}
__device__ __forceinline__ int s3i(int i, int j, int k) {
    int a = i > j ? i : j;
    int b = i > j ? j : i;
    int c;
    if (k >= a)      { c = b; b = a; a = k; }
    else if (k >= b) { c = b; b = k; }
    else             { c = k; }
    return a * (a + 1) * (a + 2) / 6 + b * (b + 1) / 2 + c;
}

// ---------------------------------------------------------------------------
// Atom phase: one thread per atom, streaming contiguous 32B/edge; register
// symmetric moments; contractions; coalesced output via smem transpose.
// ---------------------------------------------------------------------------
__global__ void __launch_bounds__(32) k_atom(float* __restrict__ outbuf) {
    __shared__ float sh[NFEAT * 33];   // padded transpose buffer (47.5 KB)

    int t = threadIdx.x;
    int a0 = blockIdx.x * 32;
    int a = a0 + t;

    if (a < NA) {
        float A0[5] = {0.f, 0.f, 0.f, 0.f, 0.f};
        float A1[5][3];
        float A2[5][6];
        float A3[5][10];
#pragma unroll
        for (int r = 0; r < 5; r++) {
#pragma unroll
            for (int u = 0; u < 3; u++) A1[r][u] = 0.f;
#pragma unroll
            for (int u = 0; u < 6; u++) A2[r][u] = 0.f;
#pragma unroll
            for (int u = 0; u < 10; u++) A3[r][u] = 0.f;
        }

        const int beg = g_off[a];
        const int end = g_off[a + 1];

#pragma unroll 2
        for (int p = beg; p < end; ++p) {
            float4 u0 = g_edata[2 * p];
            float4 u1 = g_edata[2 * p + 1];
            float radial[5] = {u0.x, u0.y, u0.z, u0.w, u1.x};
            float dnx = u1.y, dny = u1.z, dnz = u1.w;

            float g2[6] = {dnx * dnx, dny * dnx, dny * dny, dnz * dnx, dnz * dny, dnz * dnz};
            float g3[10] = {g2[0] * dnx, g2[1] * dnx, g2[2] * dnx, g2[2] * dny,
                            g2[3] * dnx, g2[4] * dnx, g2[4] * dny, g2[5] * dnx,
                            g2[5] * dny, g2[5] * dnz};
#pragma unroll
            for (int r = 0; r < 5; r++) {
                float s = radial[r];
                A0[r] += s;
                A1[r][0] += s * dnx;
                A1[r][1] += s * dny;
                A1[r][2] += s * dnz;
#pragma unroll
                for (int u = 0; u < 6; u++) A2[r][u] += s * g2[u];
#pragma unroll
                for (int u = 0; u < 10; u++) A3[r][u] += s * g3[u];
            }
        }

        // ----- contractions into shared (transposed, padded) -----
        int o = 0;
#define EMIT(v) sh[(o++) * 33 + t] = (v)

#pragma unroll
        for (int r = 0; r < 5; r++) EMIT(A0[r]);

#pragma unroll
        for (int r = 0; r < 5; r++)
#pragma unroll
            for (int s = 0; s <= r; s++) {
                float v = 0.f;
#pragma unroll
                for (int i = 0; i < 3; i++) v += A1[r][i] * A1[s][i];
                EMIT(v);
            }

        {
            const float W2[6] = {1.f, 2.f, 1.f, 2.f, 2.f, 1.f};
#pragma unroll
            for (int r = 0; r < 5; r++)
#pragma unroll
                for (int s = 0; s <= r; s++) {
                    float v = 0.f;
#pragma unroll
                    for (int u = 0; u < 6; u++) v += W2[u] * A2[r][u] * A2[s][u];
                    EMIT(v);
                }
        }

        {
            const float W3[10] = {1.f, 3.f, 3.f, 1.f, 3.f, 6.f, 3.f, 3.f, 3.f, 1.f};
#pragma unroll
            for (int r = 0; r < 5; r++)
#pragma unroll
                for (int s = 0; s <= r; s++) {
                    float v = 0.f;
#pragma unroll
                    for (int u = 0; u < 10; u++) v += W3[u] * A3[r][u] * A3[s][u];
                    EMIT(v);
                }
        }

        // c4
#pragma unroll
        for (int r = 0; r < 5; r++)
#pragma unroll
            for (int s = 0; s <= r; s++)
#pragma unroll
                for (int tt = 0; tt <= s; tt++) {
                    float v = 0.f;
#pragma unroll
                    for (int i = 0; i < 3; i++)
#pragma unroll
                        for (int j = 0; j < 3; j++)
#pragma unroll
                            for (int k = 0; k < 3; k++)
                                v += A2[r][s2i(i, j)] * A2[s][s2i(i, k)] * A2[tt][s2i(j, k)];
                    EMIT(v);
                }

        // c5
#pragma unroll
        for (int r = 0; r < 5; r++)
#pragma unroll
            for (int s = 0; s <= r; s++)
#pragma unroll
                for (int tt = 0; tt < 5; tt++) {
                    float v = 0.f;
#pragma unroll
                    for (int i = 0; i < 3; i++)
#pragma unroll
                        for (int j = 0; j < 3; j++)
                            v += A1[r][i] * A1[s][j] * A2[tt][s2i(i, j)];
                    EMIT(v);
                }

        // c6
#pragma unroll
        for (int r = 0; r < 5; r++)
#pragma unroll
            for (int s = 0; s <= r; s++) {
                float B[9];
#pragma unroll
                for (int k = 0; k < 3; k++)
#pragma unroll
                    for (int l = 0; l < 3; l++) {
                        float u = 0.f;
#pragma unroll
                        for (int i = 0; i < 3; i++)
#pragma unroll
                            for (int j = 0; j < 3; j++)
                                u += A3[r][s3i(i, j, k)] * A3[s][s3i(i, j, l)];
                        B[k * 3 + l] = u;
                    }
#pragma unroll
                for (int tt = 0; tt < 5; tt++) {
                    float v = 0.f;
#pragma unroll
                    for (int k = 0; k < 3; k++)
#pragma unroll
                        for (int l = 0; l < 3; l++)
                            v += B[k * 3 + l] * A2[tt][s2i(k, l)];
                    EMIT(v);
                }
            }

        // c7
#pragma unroll
        for (int r = 0; r < 5; r++)
#pragma unroll
            for (int s = 0; s < 5; s++) {
                float C[3];
#pragma unroll
                for (int k = 0; k < 3; k++) {
                    float u = 0.f;
#pragma unroll
                    for (int i = 0; i < 3; i++)
#pragma unroll
                        for (int j = 0; j < 3; j++)
                            u += A3[r][s3i(i, j, k)] * A2[s][s2i(i, j)];
                    C[k] = u;
                }
#pragma unroll
                for (int tt = 0; tt < 5; tt++) {
                    float v = 0.f;
#pragma unroll
                    for (int k = 0; k < 3; k++) v += C[k] * A1[tt][k];
                    EMIT(v);
                }
            }
#undef EMIT
    }

    __syncthreads();

    // cooperative coalesced copy: out[(a0+i)*360 + f] = sh[f*33 + i]
    int nat = NA - a0;
    if (nat > 32) nat = 32;
    int total = nat * NFEAT;
    for (int idx = t; idx < total; idx += 32) {
        int i = idx / NFEAT;
        int f = idx - i * NFEAT;
        outbuf[(size_t)(a0 + i) * NFEAT + f] = sh[f * 33 + i];
    }
}

extern "C" void kernel_launch(void* const* d_in, const int* in_sizes, int n_in,
                              void* d_out, int out_size) {
    const float* dr_vec = (const float*)d_in[0];
    const int*   Z      = (const int*)d_in[1];
    const int*   nbr    = (const int*)d_in[2];
    const float* emb    = (const float*)d_in[3];
    float*       out    = (float*)d_out;

    k_prep<<<(NEMB + 255) / 256, 256>>>(emb);
    k_hist<<<(NE / 4 + 255) / 256, 256>>>(nbr);
    k_scan<<<1, 1024>>>();
    k_edge<<<(NE / 2 + 255) / 256, 256>>>(dr_vec, Z, nbr);
    k_atom<<<(NA + 31) / 32, 32>>>(out);
}

// round 5
// speedup vs baseline: 1.6321x; 1.0811x over previous
#include <cuda_runtime.h>
#include <math.h>

#define NA 10000
#define NE 500000
#define NSPEC 119
#define NPAIR (NSPEC*NSPEC)      // 14161
#define EMBSTRIDE 40             // padded from 35, 160B = 16B aligned
#define NEMB (NPAIR*EMBSTRIDE)   // 566440
#define NFEAT 360

// Scratch (no allocations allowed -> device globals)
__device__ int    g_count[NA];
__device__ int    g_off[NA + 1];
__device__ int    g_cursor[NA];
__device__ float  g_emb[NEMB];
__device__ float4 g_edata[NE * 2];   // per sorted position: {r0..r3},{r4,dnx,dny,dnz}

// ---------------------------------------------------------------------------
// Prep: zero histogram + build padded/prescaled embedding table.
// ---------------------------------------------------------------------------
__global__ void k_prep(const float* __restrict__ emb) {
    int i = blockIdx.x * blockDim.x + threadIdx.x;
    if (i < NA) g_count[i] = 0;
    if (i < NEMB) {
        int pair = i / EMBSTRIDE;
        int slot = i - pair * EMBSTRIDE;
        float scale = powf(2.0f * (49.0f / 36.0f) / 3.14159265358979f, 0.75f) * rsqrtf(7.0f);
        g_emb[i] = (slot < 35) ? emb[pair * 35 + slot] * scale : 0.0f;
    }
}

// ---------------------------------------------------------------------------
// Histogram of edges per destination atom, 4 edges/thread for MLP
// ---------------------------------------------------------------------------
__global__ void k_hist(const int* __restrict__ nbr) {
    int base = (blockIdx.x * blockDim.x + threadIdx.x) * 4;
#pragma unroll
    for (int k = 0; k < 4; k++) {
        int e = base + k;
        if (e < NE) atomicAdd(&g_count[nbr[NE + e]], 1);
    }
}

// ---------------------------------------------------------------------------
// Single-block exclusive scan over 10000 counts -> offsets, cursor
// ---------------------------------------------------------------------------
__global__ void k_scan() {
    __shared__ int sh[1024];
    int t = threadIdx.x;
    const int CH = 10;
    int loc[CH];
    int sum = 0;
#pragma unroll
    for (int c = 0; c < CH; c++) {
        int idx = t * CH + c;
        loc[c] = sum;
        sum += (idx < NA) ? g_count[idx] : 0;
    }
    sh[t] = sum;
    __syncthreads();
    for (int off = 1; off < 1024; off <<= 1) {
        int v = (t >= off) ? sh[t - off] : 0;
        __syncthreads();
        sh[t] += v;
        __syncthreads();
    }
    int exc = (t > 0) ? sh[t - 1] : 0;
#pragma unroll
    for (int c = 0; c < CH; c++) {
        int idx = t * CH + c;
        if (idx < NA) {
            int o = exc + loc[c];
            g_off[idx] = o;
            g_cursor[idx] = o;
        }
    }
    if (t == 1023) g_off[NA] = sh[1023];
}

// ---------------------------------------------------------------------------
// Edge phase: fused scatter + per-edge radial/direction compute.
// Cooperative emb gather: a block stages 256 edges' coefficient rows into
// smem with consecutive chunk-ids on consecutive lanes (~4x fewer L1
// wavefronts than per-lane random LDG.128). Radial dot streams from LDS.
// ---------------------------------------------------------------------------
__global__ void __launch_bounds__(256) k_edge(const float* __restrict__ drv,
                                              const int* __restrict__ Z,
                                              const int* __restrict__ nbr) {
    __shared__ int   s_pair[256];
    __shared__ float s_q[36 * 257];   // [slot][edge], padded stride 257

    const float BETTA = 49.0f / 36.0f;
    const float PIR = 3.14159265358979f / 6.0f;
    const float SH0 = 0.5f;
    const float DSH = 5.5f / 7.0f;

    int tid = threadIdx.x;
    int e = blockIdx.x * 256 + tid;
    bool valid = (e < NE);

    int pair = 0, pos = 0;
    float x = 0.f, y = 0.f, z = 0.f;
    if (valid) {
        int ii = nbr[e];
        int jj = nbr[NE + e];
        pair = Z[ii] * NSPEC + Z[jj];
        pos = atomicAdd(&g_cursor[jj], 1);
        x = drv[3 * e + 0];
        y = drv[3 * e + 1];
        z = drv[3 * e + 2];
    }
    s_pair[tid] = pair;
    __syncthreads();

    // Cooperative gather: 2304 float4 chunks (256 edges x 9 chunks)
#pragma unroll
    for (int i = 0; i < 9; i++) {
        int id = i * 256 + tid;          // 0..2303
        int el = id / 9;                 // local edge
        int c  = id - el * 9;            // chunk 0..8
        const float4 v = *(const float4*)(g_emb + s_pair[el] * EMBSTRIDE + c * 4);
        int slot = c * 4;
        s_q[(slot + 0) * 257 + el] = v.x;
        s_q[(slot + 1) * 257 + el] = v.y;
        s_q[(slot + 2) * 257 + el] = v.z;
        s_q[(slot + 3) * 257 + el] = v.w;
    }
    __syncthreads();

    if (!valid) return;

    float dr = sqrtf(x * x + y * y + z * z);
    float inv = 1.0f / (dr + 1e-5f);
    float dnx = x * inv, dny = y * inv, dnz = z * inv;
    float cut = 0.5f * (__cosf(fminf(dr, 6.0f) * PIR) + 1.0f);

    float basis[7];
#pragma unroll
    for (int b = 0; b < 7; b++) {
        float d = dr - (SH0 + DSH * (float)b);
        basis[b] = __expf(-BETTA * d * d);
    }

    float radial[5];
#pragma unroll
    for (int r = 0; r < 5; r++) {
        float s = 0.f;
#pragma unroll
        for (int b = 0; b < 7; b++) s += s_q[(r * 7 + b) * 257 + tid] * basis[b];
        radial[r] = s * cut;
    }

    g_edata[2 * pos]     = make_float4(radial[0], radial[1], radial[2], radial[3]);
    g_edata[2 * pos + 1] = make_float4(radial[4], dnx, dny, dnz);
}

// Symmetric index helpers (fold to constants after unroll)
__device__ __forceinline__ int s2i(int i, int j) {
    return (i >= j) ? (i * (i + 1) / 2 + j) : (j * (j + 1) / 2 + i);
}
__device__ __forceinline__ int s3i(int i, int j, int k) {
    int a = i > j ? i : j;
    int b = i > j ? j : i;
    int c;
    if (k >= a)      { c = b; b = a; a = k; }
    else if (k >= b) { c = b; b = k; }
    else             { c = k; }
    return a * (a + 1) * (a + 2) / 6 + b * (b + 1) / 2 + c;
}

// ---------------------------------------------------------------------------
// Atom phase: TWO threads per atom (even/odd halves of the edge run),
// register symmetric moments, shfl-butterfly merge, contractions,
// coalesced output via smem transpose. 64 threads / 32 atoms per block.
// ---------------------------------------------------------------------------
__global__ void __launch_bounds__(64) k_atom(float* __restrict__ outbuf) {
    __shared__ float sh[NFEAT * 33];   // padded transpose buffer (47.5 KB)

    int t = threadIdx.x;        // 0..63
    int ai = t >> 1;            // local atom 0..31
    int half = t & 1;
    int a0 = blockIdx.x * 32;
    int a = a0 + ai;

    float A0[5] = {0.f, 0.f, 0.f, 0.f, 0.f};
    float A1[5][3];
    float A2[5][6];
    float A3[5][10];
#pragma unroll
    for (int r = 0; r < 5; r++) {
#pragma unroll
        for (int u = 0; u < 3; u++) A1[r][u] = 0.f;
#pragma unroll
        for (int u = 0; u < 6; u++) A2[r][u] = 0.f;
#pragma unroll
        for (int u = 0; u < 10; u++) A3[r][u] = 0.f;
    }

    if (a < NA) {
        const int beg = g_off[a];
        const int end = g_off[a + 1];
        const int mid = (beg + end) >> 1;
        const int lo = half ? mid : beg;
        const int hi = half ? end : mid;

#pragma unroll 4
        for (int p = lo; p < hi; ++p) {
            float4 u0 = g_edata[2 * p];
            float4 u1 = g_edata[2 * p + 1];
            float radial[5] = {u0.x, u0.y, u0.z, u0.w, u1.x};
            float dnx = u1.y, dny = u1.z, dnz = u1.w;

            float g2[6] = {dnx * dnx, dny * dnx, dny * dny, dnz * dnx, dnz * dny, dnz * dnz};
            float g3[10] = {g2[0] * dnx, g2[1] * dnx, g2[2] * dnx, g2[2] * dny,
                            g2[3] * dnx, g2[4] * dnx, g2[4] * dny, g2[5] * dnx,
                            g2[5] * dny, g2[5] * dnz};
#pragma unroll
            for (int r = 0; r < 5; r++) {
                float s = radial[r];
                A0[r] += s;
                A1[r][0] += s * dnx;
                A1[r][1] += s * dny;
                A1[r][2] += s * dnz;
#pragma unroll
                for (int u = 0; u < 6; u++) A2[r][u] += s * g2[u];
#pragma unroll
                for (int u = 0; u < 10; u++) A3[r][u] += s * g3[u];
            }
        }
    }

    // Butterfly merge halves (all lanes participate; both halves end up full)
#pragma unroll
    for (int r = 0; r < 5; r++) {
        A0[r] += __shfl_xor_sync(0xffffffffu, A0[r], 1);
#pragma unroll
        for (int u = 0; u < 3; u++) A1[r][u] += __shfl_xor_sync(0xffffffffu, A1[r][u], 1);
#pragma unroll
        for (int u = 0; u < 6; u++) A2[r][u] += __shfl_xor_sync(0xffffffffu, A2[r][u], 1);
#pragma unroll
        for (int u = 0; u < 10; u++) A3[r][u] += __shfl_xor_sync(0xffffffffu, A3[r][u], 1);
    }

    if (a < NA) {
        // ----- contractions into shared (transposed, padded) -----
        // Both lanes compute identical values (SIMD-free); even lane emits.
        int o = 0;
#define EMIT(v) do { if (half == 0) sh[o * 33 + ai] = (v); o++; } while (0)

#pragma unroll
        for (int r = 0; r < 5; r++) EMIT(A0[r]);

#pragma unroll
        for (int r = 0; r < 5; r++)
#pragma unroll
            for (int s = 0; s <= r; s++) {
                float v = 0.f;
#pragma unroll
                for (int i = 0; i < 3; i++) v += A1[r][i] * A1[s][i];
                EMIT(v);
            }

        {
            const float W2[6] = {1.f, 2.f, 1.f, 2.f, 2.f, 1.f};
#pragma unroll
            for (int r = 0; r < 5; r++)
#pragma unroll
                for (int s = 0; s <= r; s++) {
                    float v = 0.f;
#pragma unroll
                    for (int u = 0; u < 6; u++) v += W2[u] * A2[r][u] * A2[s][u];
                    EMIT(v);
                }
        }

        {
            const float W3[10] = {1.f, 3.f, 3.f, 1.f, 3.f, 6.f, 3.f, 3.f, 3.f, 1.f};
#pragma unroll
            for (int r = 0; r < 5; r++)
#pragma unroll
                for (int s = 0; s <= r; s++) {
                    float v = 0.f;
#pragma unroll
                    for (int u = 0; u < 10; u++) v += W3[u] * A3[r][u] * A3[s][u];
                    EMIT(v);
                }
        }

        // c4
#pragma unroll
        for (int r = 0; r < 5; r++)
#pragma unroll
            for (int s = 0; s <= r; s++)
#pragma unroll
                for (int tt = 0; tt <= s; tt++) {
                    float v = 0.f;
#pragma unroll
                    for (int i = 0; i < 3; i++)
#pragma unroll
                        for (int j = 0; j < 3; j++)
#pragma unroll
                            for (int k = 0; k < 3; k++)
                                v += A2[r][s2i(i, j)] * A2[s][s2i(i, k)] * A2[tt][s2i(j, k)];
                    EMIT(v);
                }

        // c5
#pragma unroll
        for (int r = 0; r < 5; r++)
#pragma unroll
            for (int s = 0; s <= r; s++)
#pragma unroll
                for (int tt = 0; tt < 5; tt++) {
                    float v = 0.f;
#pragma unroll
                    for (int i = 0; i < 3; i++)
#pragma unroll
                        for (int j = 0; j < 3; j++)
                            v += A1[r][i] * A1[s][j] * A2[tt][s2i(i, j)];
                    EMIT(v);
                }

        // c6
#pragma unroll
        for (int r = 0; r < 5; r++)
#pragma unroll
            for (int s = 0; s <= r; s++) {
                float B[9];
#pragma unroll
                for (int k = 0; k < 3; k++)
#pragma unroll
                    for (int l = 0; l < 3; l++) {
                        float u = 0.f;
#pragma unroll
                        for (int i = 0; i < 3; i++)
#pragma unroll
                            for (int j = 0; j < 3; j++)
                                u += A3[r][s3i(i, j, k)] * A3[s][s3i(i, j, l)];
                        B[k * 3 + l] = u;
                    }
#pragma unroll
                for (int tt = 0; tt < 5; tt++) {
                    float v = 0.f;
#pragma unroll
                    for (int k = 0; k < 3; k++)
#pragma unroll
                        for (int l = 0; l < 3; l++)
                            v += B[k * 3 + l] * A2[tt][s2i(k, l)];
                    EMIT(v);
                }
            }

        // c7
#pragma unroll
        for (int r = 0; r < 5; r++)
#pragma unroll
            for (int s = 0; s < 5; s++) {
                float C[3];
#pragma unroll
                for (int k = 0; k < 3; k++) {
                    float u = 0.f;
#pragma unroll
                    for (int i = 0; i < 3; i++)
#pragma unroll
                        for (int j = 0; j < 3; j++)
                            u += A3[r][s3i(i, j, k)] * A2[s][s2i(i, j)];
                    C[k] = u;
                }
#pragma unroll
                for (int tt = 0; tt < 5; tt++) {
                    float v = 0.f;
#pragma unroll
                    for (int k = 0; k < 3; k++) v += C[k] * A1[tt][k];
                    EMIT(v);
                }
            }
#undef EMIT
    }

    __syncthreads();

    // cooperative coalesced copy: out[(a0+i)*360 + f] = sh[f*33 + i]
    int nat = NA - a0;
    if (nat > 32) nat = 32;
    int total = nat * NFEAT;
    for (int idx = t; idx < total; idx += 64) {
        int i = idx / NFEAT;
        int f = idx - i * NFEAT;
        outbuf[(size_t)(a0 + i) * NFEAT + f] = sh[f * 33 + i];
    }
}

extern "C" void kernel_launch(void* const* d_in, const int* in_sizes, int n_in,
                              void* d_out, int out_size) {
    const float* dr_vec = (const float*)d_in[0];
    const int*   Z      = (const int*)d_in[1];
    const int*   nbr    = (const int*)d_in[2];
    const float* emb    = (const float*)d_in[3];
    float*       out    = (float*)d_out;

    k_prep<<<(NEMB + 255) / 256, 256>>>(emb);
    k_hist<<<(NE / 4 + 255) / 256, 256>>>(nbr);
    k_scan<<<1, 1024>>>();
    k_edge<<<(NE + 255) / 256, 256>>>(dr_vec, Z, nbr);
    k_atom<<<(NA + 31) / 32, 64>>>(out);
}

// round 7
// speedup vs baseline: 1.6335x; 1.0008x over previous
#include <cuda_runtime.h>
#include <math.h>

#define NA 10000
#define NE 500000
#define NSPEC 119
#define NPAIR (NSPEC*NSPEC)      // 14161
#define EMBSTRIDE 40             // padded from 35, 160B = 16B aligned
#define NEMB (NPAIR*EMBSTRIDE)   // 566440
#define NFEAT 360

// Scratch (no allocations allowed -> device globals; zero-init at module load)
__device__ int    g_count[NA];
__device__ int    g_off[NA + 1];
__device__ int    g_cursor[NA];
__device__ float  g_emb[NEMB];
__device__ float4 g_edata[NE * 2];   // per sorted position: {r0..r3},{r4,dnx,dny,dnz}

// ---------------------------------------------------------------------------
// Fused prep + hist. g_count is zero on entry: zero-initialized at load for
// the first call, re-zeroed by k_atom at the end of every pipeline run.
// ---------------------------------------------------------------------------
__global__ void k_prep_hist(const float* __restrict__ emb,
                            const int* __restrict__ nbr) {
    int i = blockIdx.x * blockDim.x + threadIdx.x;
    if (i < NEMB) {
        int pair = i / EMBSTRIDE;
        int slot = i - pair * EMBSTRIDE;
        float scale = powf(2.0f * (49.0f / 36.0f) / 3.14159265358979f, 0.75f) * rsqrtf(7.0f);
        g_emb[i] = (slot < 35) ? emb[pair * 35 + slot] * scale : 0.0f;
    }
    if (i < NE) atomicAdd(&g_count[nbr[NE + i]], 1);
}

// ---------------------------------------------------------------------------
// Single-block exclusive scan over 10000 counts -> offsets, cursor
// ---------------------------------------------------------------------------
__global__ void k_scan() {
    __shared__ int sh[1024];
    int t = threadIdx.x;
    const int CH = 10;
    int loc[CH];
    int sum = 0;
#pragma unroll
    for (int c = 0; c < CH; c++) {
        int idx = t * CH + c;
        loc[c] = sum;
        sum += (idx < NA) ? g_count[idx] : 0;
    }
    sh[t] = sum;
    __syncthreads();
    for (int off = 1; off < 1024; off <<= 1) {
        int v = (t >= off) ? sh[t - off] : 0;
        __syncthreads();
        sh[t] += v;
        __syncthreads();
    }
    int exc = (t > 0) ? sh[t - 1] : 0;
#pragma unroll
    for (int c = 0; c < CH; c++) {
        int idx = t * CH + c;
        if (idx < NA) {
            int o = exc + loc[c];
            g_off[idx] = o;
            g_cursor[idx] = o;
        }
    }
    if (t == 1023) g_off[NA] = sh[1023];
}

// ---------------------------------------------------------------------------
// Edge phase. MUFU-minimized basis:
//   basis[b] = E * A^b * B^(b^2),  E=exp(-beta*t^2), A=exp(2*beta*d*t),
//   t=dr-0.5, B=exp(-beta*d^2) (compile-time const) -> only 2 expf/edge.
// Cooperative emb gather staged as float4 rows (STS.128/LDS.128).
// ---------------------------------------------------------------------------
__global__ void __launch_bounds__(256) k_edge(const float* __restrict__ drv,
                                              const int* __restrict__ Z,
                                              const int* __restrict__ nbr) {
    __shared__ int    s_pair[256];
    __shared__ float  s_xyz[768];
    __shared__ float4 s_q4[9 * 257];   // [chunk][edge], padded stride 257

    const float BETTA = 1.36111111f;        // 49/36
    const float C1    = 2.13888889f;        // 2*betta*(5.5/7)
    const float BC    = 0.43160285f;        // exp(-betta*d^2)
    const float BC2   = 0.18628102f;        // BC^2
    const float PIR   = 0.52359877559f;     // pi/6

    int tid = threadIdx.x;
    int e = blockIdx.x * 256 + tid;
    bool valid = (e < NE);

    // coalesced dr_vec staging
    {
        int base3 = blockIdx.x * 768;
#pragma unroll
        for (int k = 0; k < 3; k++) {
            int idx = k * 256 + tid;
            if (base3 + idx < NE * 3) s_xyz[idx] = drv[base3 + idx];
        }
    }

    int pair = 0, pos = 0;
    if (valid) {
        int ii = nbr[e];
        int jj = nbr[NE + e];
        pair = Z[ii] * NSPEC + Z[jj];
        pos = atomicAdd(&g_cursor[jj], 1);
    }
    s_pair[tid] = pair;
    __syncthreads();

    // Cooperative gather: 2304 float4 chunks (256 edges x 9 chunks), one
    // STS.128 each; consecutive lanes load consecutive chunks (few lines/warp)
#pragma unroll
    for (int i = 0; i < 9; i++) {
        int id = i * 256 + tid;          // 0..2303
        int el = id / 9;                 // local edge
        int c  = id - el * 9;            // chunk 0..8
        s_q4[c * 257 + el] = *(const float4*)(g_emb + s_pair[el] * EMBSTRIDE + c * 4);
    }
    __syncthreads();

    if (!valid) return;

    float x = s_xyz[3 * tid + 0];
    float y = s_xyz[3 * tid + 1];
    float z = s_xyz[3 * tid + 2];

    float r2 = fmaxf(x * x + y * y + z * z, 1e-24f);
    float irt = rsqrtf(r2);
    float dr = r2 * irt;
    float inv = __fdividef(1.0f, dr + 1e-5f);
    float dnx = x * inv, dny = y * inv, dnz = z * inv;
    float cut = 0.5f * (__cosf(fminf(dr, 6.0f) * PIR) + 1.0f);

    // 2-expf basis chain, cutoff folded in
    float t = dr - 0.5f;
    float basis[7];
    float bas = cut * __expf(-BETTA * t * t);
    float M = __expf(C1 * t) * BC;
    basis[0] = bas;
#pragma unroll
    for (int b = 1; b < 7; b++) {
        bas *= M;
        M *= BC2;
        basis[b] = bas;
    }

    float rad[5] = {0.f, 0.f, 0.f, 0.f, 0.f};
#pragma unroll
    for (int c = 0; c < 9; c++) {
        float4 v = s_q4[c * 257 + tid];
        int s0 = 4 * c;
        { int s = s0 + 0; if (s < 35) rad[s / 7] += v.x * basis[s % 7]; }
        { int s = s0 + 1; if (s < 35) rad[s / 7] += v.y * basis[s % 7]; }
        { int s = s0 + 2; if (s < 35) rad[s / 7] += v.z * basis[s % 7]; }
        { int s = s0 + 3; if (s < 35) rad[s / 7] += v.w * basis[s % 7]; }
    }

    g_edata[2 * pos]     = make_float4(rad[0], rad[1], rad[2], rad[3]);
    g_edata[2 * pos + 1] = make_float4(rad[4], dnx, dny, dnz);
}

// Symmetric index helpers (fold to constants after unroll)
__device__ __forceinline__ int s2i(int i, int j) {
    return (i >= j) ? (i * (i + 1) / 2 + j) : (j * (j + 1) / 2 + i);
}
__device__ __forceinline__ int s3i(int i, int j, int k) {
    int a = i > j ? i : j;
    int b = i > j ? j : i;
    int c;
    if (k >= a)      { c = b; b = a; a = k; }
    else if (k >= b) { c = b; b = k; }
    else             { c = k; }
    return a * (a + 1) * (a + 2) / 6 + b * (b + 1) / 2 + c;
}

// ---------------------------------------------------------------------------
// Atom phase: FOUR threads per atom (quarter runs), register symmetric
// moments, xor-1/xor-2 butterfly merge, contractions, coalesced output.
// Also re-zeroes g_count for the next pipeline run (graph replay).
// ---------------------------------------------------------------------------
__global__ void __launch_bounds__(128) k_atom(float* __restrict__ outbuf) {
    __shared__ float sh[NFEAT * 33];   // padded transpose buffer (47.5 KB)

    int t = threadIdx.x;        // 0..127
    int ai = t >> 2;            // local atom 0..31
    int quarter = t & 3;
    int a0 = blockIdx.x * 32;
    int a = a0 + ai;

    // re-zero histogram for next launch
    {
        int gi = blockIdx.x * 128 + t;
        if (gi < NA) g_count[gi] = 0;
    }

    float A0[5] = {0.f, 0.f, 0.f, 0.f, 0.f};
    float A1[5][3];
    float A2[5][6];
    float A3[5][10];
#pragma unroll
    for (int r = 0; r < 5; r++) {
#pragma unroll
        for (int u = 0; u < 3; u++) A1[r][u] = 0.f;
#pragma unroll
        for (int u = 0; u < 6; u++) A2[r][u] = 0.f;
#pragma unroll
        for (int u = 0; u < 10; u++) A3[r][u] = 0.f;
    }

    if (a < NA) {
        const int beg = g_off[a];
        const int end = g_off[a + 1];
        const int len = end - beg;
        const int lo = beg + (len * quarter) / 4;
        const int hi = beg + (len * (quarter + 1)) / 4;

#pragma unroll 4
        for (int p = lo; p < hi; ++p) {
            float4 u0 = g_edata[2 * p];
            float4 u1 = g_edata[2 * p + 1];
            float radial[5] = {u0.x, u0.y, u0.z, u0.w, u1.x};
            float dnx = u1.y, dny = u1.z, dnz = u1.w;

            float g2[6] = {dnx * dnx, dny * dnx, dny * dny, dnz * dnx, dnz * dny, dnz * dnz};
            float g3[10] = {g2[0] * dnx, g2[1] * dnx, g2[2] * dnx, g2[2] * dny,
                            g2[3] * dnx, g2[4] * dnx, g2[4] * dny, g2[5] * dnx,
                            g2[5] * dny, g2[5] * dnz};
#pragma unroll
            for (int r = 0; r < 5; r++) {
                float s = radial[r];
                A0[r] += s;
                A1[r][0] += s * dnx;
                A1[r][1] += s * dny;
                A1[r][2] += s * dnz;
#pragma unroll
                for (int u = 0; u < 6; u++) A2[r][u] += s * g2[u];
#pragma unroll
                for (int u = 0; u < 10; u++) A3[r][u] += s * g3[u];
            }
        }
    }

    // Butterfly merge the 4 quarters (all lanes end up with the full sums)
#pragma unroll
    for (int d = 1; d <= 2; d <<= 1) {
#pragma unroll
        for (int r = 0; r < 5; r++) {
            A0[r] += __shfl_xor_sync(0xffffffffu, A0[r], d);
#pragma unroll
            for (int u = 0; u < 3; u++) A1[r][u] += __shfl_xor_sync(0xffffffffu, A1[r][u], d);
#pragma unroll
            for (int u = 0; u < 6; u++) A2[r][u] += __shfl_xor_sync(0xffffffffu, A2[r][u], d);
#pragma unroll
            for (int u = 0; u < 10; u++) A3[r][u] += __shfl_xor_sync(0xffffffffu, A3[r][u], d);
        }
    }

    if (a < NA) {
        // ----- contractions into shared (transposed, padded) -----
        // All 4 lanes compute identical values; quarter==0 lane emits.
        int o = 0;
#define EMIT(v) do { if (quarter == 0) sh[o * 33 + ai] = (v); o++; } while (0)

#pragma unroll
        for (int r = 0; r < 5; r++) EMIT(A0[r]);

#pragma unroll
        for (int r = 0; r < 5; r++)
#pragma unroll
            for (int s = 0; s <= r; s++) {
                float v = 0.f;
#pragma unroll
                for (int i = 0; i < 3; i++) v += A1[r][i] * A1[s][i];
                EMIT(v);
            }

        {
            const float W2[6] = {1.f, 2.f, 1.f, 2.f, 2.f, 1.f};
#pragma unroll
            for (int r = 0; r < 5; r++)
#pragma unroll
                for (int s = 0; s <= r; s++) {
                    float v = 0.f;
#pragma unroll
                    for (int u = 0; u < 6; u++) v += W2[u] * A2[r][u] * A2[s][u];
                    EMIT(v);
                }
        }

        {
            const float W3[10] = {1.f, 3.f, 3.f, 1.f, 3.f, 6.f, 3.f, 3.f, 3.f, 1.f};
#pragma unroll
            for (int r = 0; r < 5; r++)
#pragma unroll
                for (int s = 0; s <= r; s++) {
                    float v = 0.f;
#pragma unroll
                    for (int u = 0; u < 10; u++) v += W3[u] * A3[r][u] * A3[s][u];
                    EMIT(v);
                }
        }

        // c4
#pragma unroll
        for (int r = 0; r < 5; r++)
#pragma unroll
            for (int s = 0; s <= r; s++)
#pragma unroll
                for (int tt = 0; tt <= s; tt++) {
                    float v = 0.f;
#pragma unroll
                    for (int i = 0; i < 3; i++)
#pragma unroll
                        for (int j = 0; j < 3; j++)
#pragma unroll
                            for (int k = 0; k < 3; k++)
                                v += A2[r][s2i(i, j)] * A2[s][s2i(i, k)] * A2[tt][s2i(j, k)];
                    EMIT(v);
                }

        // c5
#pragma unroll
        for (int r = 0; r < 5; r++)
#pragma unroll
            for (int s = 0; s <= r; s++)
#pragma unroll
                for (int tt = 0; tt < 5; tt++) {
                    float v = 0.f;
#pragma unroll
                    for (int i = 0; i < 3; i++)
#pragma unroll
                        for (int j = 0; j < 3; j++)
                            v += A1[r][i] * A1[s][j] * A2[tt][s2i(i, j)];
                    EMIT(v);
                }

        // c6
#pragma unroll
        for (int r = 0; r < 5; r++)
#pragma unroll
            for (int s = 0; s <= r; s++) {
                float B[9];
#pragma unroll
                for (int k = 0; k < 3; k++)
#pragma unroll
                    for (int l = 0; l < 3; l++) {
                        float u = 0.f;
#pragma unroll
                        for (int i = 0; i < 3; i++)
#pragma unroll
                            for (int j = 0; j < 3; j++)
                                u += A3[r][s3i(i, j, k)] * A3[s][s3i(i, j, l)];
                        B[k * 3 + l] = u;
                    }
#pragma unroll
                for (int tt = 0; tt < 5; tt++) {
                    float v = 0.f;
#pragma unroll
                    for (int k = 0; k < 3; k++)
#pragma unroll
                        for (int l = 0; l < 3; l++)
                            v += B[k * 3 + l] * A2[tt][s2i(k, l)];
                    EMIT(v);
                }
            }

        // c7
#pragma unroll
        for (int r = 0; r < 5; r++)
#pragma unroll
            for (int s = 0; s < 5; s++) {
                float C[3];
#pragma unroll
                for (int k = 0; k < 3; k++) {
                    float u = 0.f;
#pragma unroll
                    for (int i = 0; i < 3; i++)
#pragma unroll
                        for (int j = 0; j < 3; j++)
                            u += A3[r][s3i(i, j, k)] * A2[s][s2i(i, j)];
                    C[k] = u;
                }
#pragma unroll
                for (int tt = 0; tt < 5; tt++) {
                    float v = 0.f;
#pragma unroll
                    for (int k = 0; k < 3; k++) v += C[k] * A1[tt][k];
                    EMIT(v);
                }
            }
#undef EMIT
    }

    __syncthreads();

    // cooperative coalesced copy: out[(a0+i)*360 + f] = sh[f*33 + i]
    int nat = NA - a0;
    if (nat > 32) nat = 32;
    int total = nat * NFEAT;
    for (int idx = t; idx < total; idx += 128) {
        int i = idx / NFEAT;
        int f = idx - i * NFEAT;
        outbuf[(size_t)(a0 + i) * NFEAT + f] = sh[f * 33 + i];
    }
}

extern "C" void kernel_launch(void* const* d_in, const int* in_sizes, int n_in,
                              void* d_out, int out_size) {
    const float* dr_vec = (const float*)d_in[0];
    const int*   Z      = (const int*)d_in[1];
    const int*   nbr    = (const int*)d_in[2];
    const float* emb    = (const float*)d_in[3];
    float*       out    = (float*)d_out;

    k_prep_hist<<<(NEMB + 255) / 256, 256>>>(emb, nbr);
    k_scan<<<1, 1024>>>();
    k_edge<<<(NE + 255) / 256, 256>>>(dr_vec, Z, nbr);
    k_atom<<<(NA + 31) / 32, 128>>>(out);
}